// round 6
// baseline (speedup 1.0000x reference)
#include <cuda_runtime.h>
#include <cuda_bf16.h>

#define NUM_CLASSES 601
#define OUT_DIM 27
#define PAD_DIM 32          // pad rows to 32 floats = 128 B = exactly one L1 line

// Precomputed softmax table: 601 rows x 32 floats (cols 27..31 = 0 padding).
// 601*32*4 = 76,928 B -> fully L1-resident per SM.
__device__ __align__(128) float g_table[NUM_CLASSES * PAD_DIM];

// ---------------------------------------------------------------------------
// Kernel A: build softmax table. One warp per class row.
// Matches reference exactly: probs = exp(logits) / sum(exp(logits)).
// ---------------------------------------------------------------------------
__global__ void softmax_table_kernel(const float* __restrict__ W) {
    int r = blockIdx.x;          // 0..600
    int c = threadIdx.x;         // 0..31
    float e = 0.0f;
    if (c < OUT_DIM) {
        e = expf(W[r * OUT_DIM + c]);
    }
    float s = e;
    #pragma unroll
    for (int off = 16; off > 0; off >>= 1)
        s += __shfl_xor_sync(0xffffffffu, s, off);
    g_table[r * PAD_DIM + c] = (c < OUT_DIM) ? (e / s) : 0.0f;
}

// ---------------------------------------------------------------------------
// Kernel B: direct output-element-parallel gather.
// Thread -> one output float. Within a warp the 32 consecutive output
// elements span at most 2 logical rows, so:
//   idx load     : 1 L1 wavefront  (same line)
//   table gather : <=2 wavefronts  (each padded row = 1 line)
//   store        : 1 wavefront     (128B contiguous STG.32)
// No shared memory, no syncthreads.
// ---------------------------------------------------------------------------
__global__ void __launch_bounds__(256) gather_direct_kernel(
    const int* __restrict__ idx, float* __restrict__ out, int total)
{
    int e = blockIdx.x * blockDim.x + threadIdx.x;
    if (e >= total) return;
    int row = e / OUT_DIM;                 // compiler -> mulhi + shift
    int col = e - row * OUT_DIM;
    int r = __ldg(idx + row);
    out[e] = g_table[r * PAD_DIM + col];
}

extern "C" void kernel_launch(void* const* d_in, const int* in_sizes, int n_in,
                              void* d_out, int out_size) {
    const int* idx;
    const float* W;
    int batch;
    if (in_sizes[0] == NUM_CLASSES * OUT_DIM) {
        W = (const float*)d_in[0];
        idx = (const int*)d_in[1];
        batch = in_sizes[1];
    } else {
        idx = (const int*)d_in[0];
        W = (const float*)d_in[1];
        batch = in_sizes[0];
    }

    softmax_table_kernel<<<NUM_CLASSES, 32>>>(W);

    int total = batch * OUT_DIM;           // 113,246,208 < 2^31
    int nblocks = (total + 255) / 256;
    gather_direct_kernel<<<nblocks, 256>>>(idx, (float*)d_out, total);
}

// round 7
// speedup vs baseline: 3.3103x; 3.3103x over previous
#include <cuda_runtime.h>
#include <cuda_bf16.h>

#define NUM_CLASSES 601
#define OUT_DIM 27
#define PAD_DIM 32          // pad rows to 32 floats = 128 B = exactly one L1 line

// Precomputed softmax table: 601 rows x 32 floats (cols 27..31 = 0 padding).
// 601*32*4 = 76,928 B -> L1/L2 resident.
__device__ __align__(128) float g_table[NUM_CLASSES * PAD_DIM];

// ---------------------------------------------------------------------------
// Kernel A: build softmax table. One warp per class row.
// Matches reference exactly: probs = exp(logits) / sum(exp(logits)).
// ---------------------------------------------------------------------------
__global__ void softmax_table_kernel(const float* __restrict__ W) {
    int r = blockIdx.x;          // 0..600
    int c = threadIdx.x;         // 0..31
    float e = 0.0f;
    if (c < OUT_DIM) {
        e = expf(W[r * OUT_DIM + c]);
    }
    float s = e;
    #pragma unroll
    for (int off = 16; off > 0; off >>= 1)
        s += __shfl_xor_sync(0xffffffffu, s, off);
    g_table[r * PAD_DIM + c] = (c < OUT_DIM) ? (e / s) : 0.0f;
}

// ---------------------------------------------------------------------------
// Kernel B: warp-cooperative gather.
// Each warp handles 32 consecutive output rows:
//   - 1 coalesced LDG for the 32 indices
//   - per row: broadcast index via shfl, all lanes read ONE 128B table line
//     (1 L1 wavefront), lanes 0..26 store the 27 output floats (~1.8 wf).
// The 32 row-chains in the unrolled loop are independent -> MLP ~32,
// hiding the L1/L2 gather latency that killed the previous version.
// ---------------------------------------------------------------------------
__global__ void __launch_bounds__(256) gather_warp_kernel(
    const int* __restrict__ idx, float* __restrict__ out, int batch)
{
    const int lane = threadIdx.x & 31;
    const int warp = threadIdx.x >> 5;
    const long long base = ((long long)blockIdx.x * 8 + warp) * 32;
    if (base >= batch) return;

    const long long nrows = batch - base;   // >=1
    int myidx = 0;
    if (base + lane < batch) myidx = __ldg(idx + base + lane);

    float* orow = out + base * OUT_DIM + lane;

    if (nrows >= 32) {
        #pragma unroll
        for (int j = 0; j < 32; j++) {
            int rj = __shfl_sync(0xffffffffu, myidx, j);
            float v = g_table[rj * PAD_DIM + lane];
            if (lane < OUT_DIM) orow[j * OUT_DIM] = v;
        }
    } else {
        for (int j = 0; j < (int)nrows; j++) {
            int rj = __shfl_sync(0xffffffffu, myidx, j);
            float v = g_table[rj * PAD_DIM + lane];
            if (lane < OUT_DIM) orow[j * OUT_DIM] = v;
        }
    }
}

extern "C" void kernel_launch(void* const* d_in, const int* in_sizes, int n_in,
                              void* d_out, int out_size) {
    const int* idx;
    const float* W;
    int batch;
    if (in_sizes[0] == NUM_CLASSES * OUT_DIM) {
        W = (const float*)d_in[0];
        idx = (const int*)d_in[1];
        batch = in_sizes[1];
    } else {
        idx = (const int*)d_in[0];
        W = (const float*)d_in[1];
        batch = in_sizes[0];
    }

    softmax_table_kernel<<<NUM_CLASSES, 32>>>(W);

    // 8 warps/block, 32 rows/warp -> 256 rows per block
    long long nblocks = ((long long)batch + 255) / 256;
    gather_warp_kernel<<<(int)nblocks, 256>>>(idx, (float*)d_out, batch);
}